// round 1
// baseline (speedup 1.0000x reference)
#include <cuda_runtime.h>
#include <math.h>

#define NB      1024
#define HID     128
#define DIM     16
#define NSTEPS  10

// Intermediate storage (device globals: no allocation allowed)
__device__ float g_y [NB*DIM];
__device__ float g_ys[NB*DIM];
__device__ float g_V [NB*DIM*DIM];   // g_V[p][dir j][comp i] = J[i][j]

struct WS {
  float dH[16][128];     // tangent activations (16 dirs x 128 hidden)
  float vin[16][16];     // stage tangent input
  float v[16][16];       // tangent state (columns of J, dir-major)
  float u[16][16];       // last stage tangent output
  float hJ[128];         // primal hidden (J-point)
  float hS[128];         // primal hidden (star point)
  float z[16], zin[16], kst[16], ksum[16];
  float zs[16], zins[16], ksts[16], ksums[16];
};
// sizeof(WS) = 3200 floats = 12800 bytes

__global__ __launch_bounds__(256)
void flow_jac_kernel(const float* __restrict__ x,  const float* __restrict__ xs,
                     const float* __restrict__ W0, const float* __restrict__ b0,
                     const float* __restrict__ W1, const float* __restrict__ b1,
                     const float* __restrict__ W2, const float* __restrict__ b2,
                     const float* __restrict__ W3, const float* __restrict__ b3,
                     const float* __restrict__ W4, const float* __restrict__ b4)
{
  extern __shared__ unsigned char smem_raw[];
  const int warp = threadIdx.x >> 5;
  const int lane = threadIdx.x & 31;
  WS* ws = reinterpret_cast<WS*>(smem_raw) + warp;
  const int p = blockIdx.x * 8 + warp;   // grid 128 * 8 warps = 1024 exactly

  const int c0 = lane, c1 = lane + 32, c2 = lane + 64, c3 = lane + 96;
  const int dlane = lane & 15;
  const int r0 = (lane >> 4) * 8;

  // ---- init state ----
  if (lane < 16) {
    ws->z [lane] = x [p*DIM + lane];
    ws->zs[lane] = xs[p*DIM + lane];
  }
  #pragma unroll
  for (int e = lane; e < 256; e += 32)
    ws->v[e >> 4][e & 15] = ((e >> 4) == (e & 15)) ? 1.f : 0.f;
  __syncwarp();

  const float dt = 1.f / NSTEPS;

  for (int step = 0; step < NSTEPS; ++step) {
    const float t0 = step * dt;
    if (lane < 16) { ws->ksum[lane] = 0.f; ws->ksums[lane] = 0.f; }
    float usum[8];
    #pragma unroll
    for (int i = 0; i < 8; ++i) usum[i] = 0.f;

    for (int s = 0; s < 4; ++s) {
      const float cs  = (s == 0) ? 0.f : ((s == 3) ? dt : 0.5f * dt);
      const float ts  = t0 + cs;                 // stage time offset == cs
      const float wgt = (s == 0 || s == 3) ? 1.f : 2.f;

      // stage inputs
      if (lane < 16) {
        float kk  = (s == 0) ? 0.f : ws->kst [lane];
        float kks = (s == 0) ? 0.f : ws->ksts[lane];
        ws->zin [lane] = ws->z [lane] + cs * kk;
        ws->zins[lane] = ws->zs[lane] + cs * kks;
      }
      #pragma unroll
      for (int e = lane; e < 256; e += 32) {
        int rr = e >> 4, cc = e & 15;
        float uu = (s == 0) ? 0.f : ws->u[rr][cc];
        ws->vin[rr][cc] = ws->v[rr][cc] + cs * uu;
      }
      __syncwarp();

      // ================= PRIMAL (J point + star point) =================
      float aL[4][4];
      {
        float accJ[4], accS[4];
        #pragma unroll
        for (int j = 0; j < 4; ++j) { float bb = b0[c0 + 32*j]; accJ[j] = bb; accS[j] = bb; }
        #pragma unroll
        for (int k = 0; k < 16; ++k) {
          float zi = ws->zin[k], zis = ws->zins[k];
          #pragma unroll
          for (int j = 0; j < 4; ++j) {
            float w = W0[k*HID + c0 + 32*j];
            accJ[j] += zi * w; accS[j] += zis * w;
          }
        }
        #pragma unroll
        for (int j = 0; j < 4; ++j) {
          float w = W0[16*HID + c0 + 32*j];
          accJ[j] += ts * w; accS[j] += ts * w;
          float h = tanhf(accJ[j]);
          aL[0][j] = 1.f - h*h;
          ws->hJ[c0 + 32*j] = h;
          ws->hS[c0 + 32*j] = tanhf(accS[j]);
        }
      }
      __syncwarp();

      #pragma unroll
      for (int l = 0; l < 3; ++l) {
        const float* Wl = (l == 0) ? W1 : ((l == 1) ? W2 : W3);
        const float* bl = (l == 0) ? b1 : ((l == 1) ? b2 : b3);
        float accJ[4], accS[4];
        #pragma unroll
        for (int j = 0; j < 4; ++j) { float bb = bl[c0 + 32*j]; accJ[j] = bb; accS[j] = bb; }
        #pragma unroll 1
        for (int kg = 0; kg < 32; ++kg) {
          int kb = kg * 4;
          float4 hj = *reinterpret_cast<const float4*>(&ws->hJ[kb]);
          float4 hs = *reinterpret_cast<const float4*>(&ws->hS[kb]);
          const float* wr0 = Wl + kb*HID + c0;
          #pragma unroll
          for (int j = 0; j < 4; ++j) {
            float w0 = wr0[0*HID + 32*j], w1 = wr0[1*HID + 32*j];
            float w2 = wr0[2*HID + 32*j], w3 = wr0[3*HID + 32*j];
            accJ[j] += hj.x*w0 + hj.y*w1 + hj.z*w2 + hj.w*w3;
            accS[j] += hs.x*w0 + hs.y*w1 + hs.z*w2 + hs.w*w3;
          }
        }
        __syncwarp();
        #pragma unroll
        for (int j = 0; j < 4; ++j) {
          float h = tanhf(accJ[j]);
          aL[l+1][j] = 1.f - h*h;
          ws->hJ[c0 + 32*j] = h;
          ws->hS[c0 + 32*j] = tanhf(accS[j]);
        }
        __syncwarp();
      }

      // primal output layer: lanes 0-15 -> J point, lanes 16-31 -> star point
      {
        const float* hb = (lane < 16) ? ws->hJ : ws->hS;
        float acc = b4[dlane];
        #pragma unroll 1
        for (int kg = 0; kg < 32; ++kg) {
          int kb = kg * 4;
          float4 h4 = *reinterpret_cast<const float4*>(&hb[kb]);
          acc += h4.x * W4[(kb+0)*DIM + dlane] + h4.y * W4[(kb+1)*DIM + dlane]
               + h4.z * W4[(kb+2)*DIM + dlane] + h4.w * W4[(kb+3)*DIM + dlane];
        }
        if (lane < 16) { ws->kst [dlane] = acc; ws->ksum [dlane] += wgt * acc; }
        else           { ws->ksts[dlane] = acc; ws->ksums[dlane] += wgt * acc; }
      }
      __syncwarp();

      // ================= TANGENT (16 directions, JVP through MLP) =================
      // layer 0: vin(16x16) @ W0[0:16,:]  (t-tangent = 0), scale by a0
      {
        float acc[64];
        #pragma unroll
        for (int i = 0; i < 64; ++i) acc[i] = 0.f;
        #pragma unroll 1
        for (int kg = 0; kg < 4; ++kg) {
          int kb = kg * 4;
          float w[16];
          #pragma unroll
          for (int kk = 0; kk < 4; ++kk) {
            const float* wr = W0 + (kb+kk)*HID + c0;
            w[kk*4+0] = wr[0]; w[kk*4+1] = wr[32]; w[kk*4+2] = wr[64]; w[kk*4+3] = wr[96];
          }
          #pragma unroll
          for (int r = 0; r < 16; ++r) {
            float4 vv = *reinterpret_cast<const float4*>(&ws->vin[r][kb]);
            #pragma unroll
            for (int j = 0; j < 4; ++j)
              acc[r*4+j] += vv.x*w[j] + vv.y*w[4+j] + vv.z*w[8+j] + vv.w*w[12+j];
          }
        }
        __syncwarp();
        #pragma unroll
        for (int r = 0; r < 16; ++r) {
          ws->dH[r][c0] = aL[0][0] * acc[r*4+0];
          ws->dH[r][c1] = aL[0][1] * acc[r*4+1];
          ws->dH[r][c2] = aL[0][2] * acc[r*4+2];
          ws->dH[r][c3] = aL[0][3] * acc[r*4+3];
        }
        __syncwarp();
      }

      // layers 1..3: dH <- a_l * (dH @ Wl)
      #pragma unroll
      for (int l = 0; l < 3; ++l) {
        const float* Wl = (l == 0) ? W1 : ((l == 1) ? W2 : W3);
        float acc[64];
        #pragma unroll
        for (int i = 0; i < 64; ++i) acc[i] = 0.f;
        #pragma unroll 1
        for (int kg = 0; kg < 32; ++kg) {
          int kb = kg * 4;
          float w[16];
          #pragma unroll
          for (int kk = 0; kk < 4; ++kk) {
            const float* wr = Wl + (kb+kk)*HID + c0;
            w[kk*4+0] = wr[0]; w[kk*4+1] = wr[32]; w[kk*4+2] = wr[64]; w[kk*4+3] = wr[96];
          }
          #pragma unroll
          for (int r = 0; r < 16; ++r) {
            float4 dd = *reinterpret_cast<const float4*>(&ws->dH[r][kb]);
            #pragma unroll
            for (int j = 0; j < 4; ++j)
              acc[r*4+j] += dd.x*w[j] + dd.y*w[4+j] + dd.z*w[8+j] + dd.w*w[12+j];
          }
        }
        __syncwarp();   // all lanes done reading dH before overwrite
        #pragma unroll
        for (int r = 0; r < 16; ++r) {
          ws->dH[r][c0] = aL[l+1][0] * acc[r*4+0];
          ws->dH[r][c1] = aL[l+1][1] * acc[r*4+1];
          ws->dH[r][c2] = aL[l+1][2] * acc[r*4+2];
          ws->dH[r][c3] = aL[l+1][3] * acc[r*4+3];
        }
        __syncwarp();
      }

      // tangent output layer: u[r][d] = dH[r][:] @ W4[:,d]
      {
        float acc8[8];
        #pragma unroll
        for (int i = 0; i < 8; ++i) acc8[i] = 0.f;
        #pragma unroll 1
        for (int kg = 0; kg < 32; ++kg) {
          int kb = kg * 4;
          float w0 = W4[(kb+0)*DIM + dlane], w1 = W4[(kb+1)*DIM + dlane];
          float w2 = W4[(kb+2)*DIM + dlane], w3 = W4[(kb+3)*DIM + dlane];
          #pragma unroll
          for (int rr = 0; rr < 8; ++rr) {
            float4 dd = *reinterpret_cast<const float4*>(&ws->dH[r0+rr][kb]);
            acc8[rr] += dd.x*w0 + dd.y*w1 + dd.z*w2 + dd.w*w3;
          }
        }
        __syncwarp();
        #pragma unroll
        for (int rr = 0; rr < 8; ++rr) {
          ws->u[r0+rr][dlane] = acc8[rr];
          usum[rr] += wgt * acc8[rr];
        }
        __syncwarp();
      }
    } // stage loop

    // RK4 state update
    const float f = dt / 6.f;
    if (lane < 16) {
      ws->z [lane] += f * ws->ksum [lane];
      ws->zs[lane] += f * ws->ksums[lane];
    }
    #pragma unroll
    for (int rr = 0; rr < 8; ++rr)
      ws->v[r0+rr][dlane] += f * usum[rr];
    __syncwarp();
  } // step loop

  // write results
  if (lane < 16) {
    g_y [p*DIM + lane] = ws->z [lane];
    g_ys[p*DIM + lane] = ws->zs[lane];
  }
  #pragma unroll
  for (int e = lane; e < 256; e += 32)
    g_V[p*256 + e] = ws->v[e >> 4][e & 15];
}

// =========================== finalize ===========================
// per point: g = (y - y*)/(|y-y*|+1e-8); gx = J^T g; G = J^T J;
// solve (G + 1e-6 I) s = gx (Cholesky);  out = -s
__global__ void finalize_kernel(float* __restrict__ out)
{
  int p = blockIdx.x * blockDim.x + threadIdx.x;
  if (p >= NB) return;

  float gph[16]; float n2 = 0.f;
  #pragma unroll
  for (int i = 0; i < 16; ++i) {
    float d = g_y[p*DIM + i] - g_ys[p*DIM + i];
    gph[i] = d; n2 += d * d;
  }
  float inv = 1.f / (sqrtf(n2) + 1e-8f);
  #pragma unroll
  for (int i = 0; i < 16; ++i) gph[i] *= inv;

  float Vr[16][16];
  const float* V = g_V + p * 256;
  for (int j = 0; j < 16; ++j)
    for (int i = 0; i < 16; ++i) Vr[j][i] = V[j*16 + i];

  float gx[16];
  for (int j = 0; j < 16; ++j) {
    float sacc = 0.f;
    for (int i = 0; i < 16; ++i) sacc += Vr[j][i] * gph[i];
    gx[j] = sacc;
  }

  float G[16][16];
  for (int j = 0; j < 16; ++j)
    for (int k = 0; k <= j; ++k) {
      float sacc = 0.f;
      for (int i = 0; i < 16; ++i) sacc += Vr[j][i] * Vr[k][i];
      G[j][k] = sacc; G[k][j] = sacc;
    }
  for (int j = 0; j < 16; ++j) G[j][j] += 1e-6f;

  // in-place Cholesky (lower)
  for (int j = 0; j < 16; ++j) {
    float d = G[j][j];
    for (int k = 0; k < j; ++k) d -= G[j][k] * G[j][k];
    d = sqrtf(fmaxf(d, 1e-30f));
    G[j][j] = d;
    float id = 1.f / d;
    for (int i = j + 1; i < 16; ++i) {
      float sacc = G[i][j];
      for (int k = 0; k < j; ++k) sacc -= G[i][k] * G[j][k];
      G[i][j] = sacc * id;
    }
  }
  // forward solve L yv = gx
  float yv[16];
  for (int i = 0; i < 16; ++i) {
    float sacc = gx[i];
    for (int k = 0; k < i; ++k) sacc -= G[i][k] * yv[k];
    yv[i] = sacc / G[i][i];
  }
  // back solve L^T s = yv
  float sol[16];
  for (int i = 15; i >= 0; --i) {
    float sacc = yv[i];
    for (int k = i + 1; k < 16; ++k) sacc -= G[k][i] * sol[k];
    sol[i] = sacc / G[i][i];
  }
  for (int j = 0; j < 16; ++j) out[p*DIM + j] = -sol[j];
}

extern "C" void kernel_launch(void* const* d_in, const int* in_sizes, int n_in,
                              void* d_out, int out_size)
{
  const float* x  = (const float*)d_in[0];
  const float* xs = (const float*)d_in[1];
  const float* W0 = (const float*)d_in[2];
  const float* b0 = (const float*)d_in[3];
  const float* W1 = (const float*)d_in[4];
  const float* b1 = (const float*)d_in[5];
  const float* W2 = (const float*)d_in[6];
  const float* b2 = (const float*)d_in[7];
  const float* W3 = (const float*)d_in[8];
  const float* b3 = (const float*)d_in[9];
  const float* W4 = (const float*)d_in[10];
  const float* b4 = (const float*)d_in[11];
  float* out = (float*)d_out;

  size_t sh = sizeof(WS) * 8;  // 8 warps per CTA = 102400 bytes
  cudaFuncSetAttribute(flow_jac_kernel, cudaFuncAttributeMaxDynamicSharedMemorySize, (int)sh);

  flow_jac_kernel<<<128, 256, sh>>>(x, xs, W0, b0, W1, b1, W2, b2, W3, b3, W4, b4);
  finalize_kernel<<<8, 128>>>(out);
}